// round 6
// baseline (speedup 1.0000x reference)
#include <cuda_runtime.h>
#include <cstdint>

// EntailmentConeLoss: loss = 0.5*( mean_i E(p_i,cpos_i) + mean_{i,k} relu(MARGIN - E(p_i,cneg_{ik})) )
// E(p,c) = relu(acos(clip(num/denom)) - asin(clip(BETA/(|p|+eps),0,1-eps)))
// dot form: num = 2*(dot - |p|^2); |c-p|^2 = |c|^2 + |p|^2 - 2*dot; denom = 2*sqrt(sp2*sd2)+eps
//
// Mapping: one warp per pair, split into TWO 16-lane groups. Each lane owns a
// 16-float slice of D=256 (4x float4, stride-16 float4s for coalescing; both
// groups read identical p addresses -> HW broadcast dedup). Each pass reduces
// TWO rows with one 4-stage butterfly and one epilogue stream.

#define C_CONST 100000
#define D_CONST 256
#define P_CONST 65536
#define K_CONST 4
#define BETA 0.1f
#define MARGIN 0.1f
#define EPS 1e-6f

#define WARPS_PER_BLOCK 8
#define THREADS_PER_BLOCK (WARPS_PER_BLOCK * 32)
#define NUM_BLOCKS (P_CONST / WARPS_PER_BLOCK)   // 8192

#define WPOS (0.5f / (float)P_CONST)
#define WNEG (0.5f / ((float)P_CONST * (float)K_CONST))

__device__ __align__(16) float g_partials[NUM_BLOCKS];
__device__ unsigned int g_count;   // zero-init; last block resets each call

__device__ __forceinline__ float sqrt_approx(float x) {
    float r; asm("sqrt.approx.f32 %0, %1;" : "=f"(r) : "f"(x)); return r;
}
__device__ __forceinline__ float rcp_approx(float x) {
    float r; asm("rcp.approx.f32 %0, %1;" : "=f"(r) : "f"(x)); return r;
}
__device__ __forceinline__ float dot4(float4 a, float4 b) {
    return a.x*b.x + a.y*b.y + a.z*b.z + a.w*b.w;
}

__global__ __launch_bounds__(THREADS_PER_BLOCK, 4)
void cone_loss_kernel(const float* __restrict__ protos,
                      const int*   __restrict__ pairs,
                      const int*   __restrict__ neg_c,
                      float*       __restrict__ out) {
    const int wid  = threadIdx.x >> 5;
    const int lane = threadIdx.x & 31;
    const int g    = lane >> 4;     // group 0/1 within warp
    const int s    = lane & 15;     // slice within group
    const int pair = blockIdx.x * WARPS_PER_BLOCK + wid;   // one warp per pair

    __shared__ float s_warp[WARPS_PER_BLOCK];

    // ---- indices (uniform per warp) ----
    const int2 pc   = __ldg(reinterpret_cast<const int2*>(pairs) + pair);
    const int4 nidx = __ldg(reinterpret_cast<const int4*>(neg_c) + pair);

    // ---- p row: 4x float4 per lane, float4 index = s + 16*i (coalesced per group;
    //      groups read identical addresses -> broadcast) ----
    const float4* pbase = reinterpret_cast<const float4*>(protos);
    const float4* prow  = pbase + (size_t)pc.x * (D_CONST / 4);
    const float4 p0 = __ldg(prow + s);
    const float4 p1 = __ldg(prow + s + 16);
    const float4 p2 = __ldg(prow + s + 32);
    const float4 p3 = __ldg(prow + s + 48);

    float sp2p = dot4(p0,p0) + dot4(p1,p1) + dot4(p2,p2) + dot4(p3,p3);
    #pragma unroll
    for (int o = 1; o < 16; o <<= 1) sp2p += __shfl_xor_sync(0xFFFFFFFFu, sp2p, o);
    const float sp2    = sp2p;
    const float norm_p = sqrt_approx(sp2);

    // aperture: asin(sa), sa ~ 0.006 -> cubic Taylor (|err| < 1e-11)
    float sa = BETA / (norm_p + EPS);
    sa = fminf(fmaxf(sa, 0.0f), 1.0f - EPS);
    const float aperture = sa * (1.0f + sa * sa * (1.0f / 6.0f));

    // ---- energy of one c-row, reduced within this lane's 16-lane group ----
    auto energy = [&](int cidx) -> float {
        const float4* crow = pbase + (size_t)cidx * (D_CONST / 4);
        float4 c0 = __ldg(crow + s);
        float4 c1 = __ldg(crow + s + 16);
        float4 c2 = __ldg(crow + s + 32);
        float4 c3 = __ldg(crow + s + 48);
        float ccp = dot4(c0,c0) + dot4(c1,c1) + dot4(c2,c2) + dot4(c3,c3);
        float dtp = dot4(c0,p0) + dot4(c1,p1) + dot4(c2,p2) + dot4(c3,p3);
        #pragma unroll
        for (int o = 1; o < 16; o <<= 1) {   // 4 stages, stays within group
            ccp += __shfl_xor_sync(0xFFFFFFFFu, ccp, o);
            dtp += __shfl_xor_sync(0xFFFFFFFFu, dtp, o);
        }
        float sd2 = fmaxf(ccp + sp2 - 2.0f * dtp, 0.0f);
        float num = 2.0f * (dtp - sp2);
        float denom  = 2.0f * sqrt_approx(sp2 * sd2) + EPS;  // sqrt.approx(0)=0 -> c==p edge OK
        float cosang = num * rcp_approx(denom);
        cosang = fminf(fmaxf(cosang, -1.0f + EPS), 1.0f - EPS);
        return fmaxf(acosf(cosang) - aperture, 0.0f);
    };

    float acc = 0.0f;
    // pass 0: g0 -> positive row, g1 -> neg0
    {
        float e = energy(g ? nidx.x : pc.y);
        acc += g ? fmaxf(MARGIN - e, 0.0f) * WNEG : e * WPOS;
    }
    // pass 1: g0 -> neg1, g1 -> neg2
    {
        float e = energy(g ? nidx.z : nidx.y);
        acc += fmaxf(MARGIN - e, 0.0f) * WNEG;
    }
    // pass 2: both groups -> neg3 (g1 duplicate, weight 0; loads dedup across groups)
    {
        float e = energy(nidx.w);
        acc += g ? 0.0f : fmaxf(MARGIN - e, 0.0f) * WNEG;
    }
    // combine the two groups (all lanes in a group hold identical acc)
    acc += __shfl_xor_sync(0xFFFFFFFFu, acc, 16);

    if (lane == 0) s_warp[wid] = acc;
    __syncthreads();

    // ---- per-block partial -> L2 via st.cg, release-acquire counter (no threadfence) ----
    __shared__ bool is_last;
    if (threadIdx.x == 0) {
        float bsum = 0.0f;
        #pragma unroll
        for (int w = 0; w < WARPS_PER_BLOCK; w++) bsum += s_warp[w];
        asm volatile("st.global.cg.f32 [%0], %1;"
                     :: "l"(&g_partials[blockIdx.x]), "f"(bsum) : "memory");
        unsigned int old;
        asm volatile("atom.acq_rel.gpu.global.add.u32 %0, [%1], %2;"
                     : "=r"(old) : "l"(&g_count), "r"(1u) : "memory");
        is_last = (old == (unsigned int)(NUM_BLOCKS - 1));
    }
    __syncthreads();

    // ---- last block: reduce 8192 partials from L2 ----
    if (is_last) {
        const float4* src = reinterpret_cast<const float4*>(g_partials);
        float r = 0.0f;
        #pragma unroll
        for (int j = 0; j < 8; j++) {   // 2048 float4 = 256 thr * 8
            float4 v = __ldcg(&src[threadIdx.x + j * THREADS_PER_BLOCK]);
            r += (v.x + v.y) + (v.z + v.w);
        }
        #pragma unroll
        for (int o = 16; o > 0; o >>= 1) r += __shfl_xor_sync(0xFFFFFFFFu, r, o);
        if (lane == 0) s_warp[wid] = r;
        __syncthreads();
        if (threadIdx.x == 0) {
            float tot = 0.0f;
            #pragma unroll
            for (int w = 0; w < WARPS_PER_BLOCK; w++) tot += s_warp[w];
            out[0] = tot;
            atomicExch(&g_count, 0u);   // reset for next graph replay
        }
    }
}

extern "C" void kernel_launch(void* const* d_in, const int* in_sizes, int n_in,
                              void* d_out, int out_size) {
    const float* protos = (const float*)d_in[0];
    const int*   pairs  = (const int*)d_in[1];
    const int*   negc   = (const int*)d_in[2];
    float* out = (float*)d_out;

    cone_loss_kernel<<<NUM_BLOCKS, THREADS_PER_BLOCK>>>(protos, pairs, negc, out);
}

// round 7
// speedup vs baseline: 1.2079x; 1.2079x over previous
#include <cuda_runtime.h>
#include <cstdint>

// EntailmentConeLoss: loss = 0.5*( mean_i E(p_i,cpos_i) + mean_{i,k} relu(MARGIN - E(p_i,cneg_{ik})) )
// E(p,c) = relu(acos(clip(num/denom)) - asin(clip(BETA/(|p|+eps),0,1-eps)))
// dot form: num = 2*(dot - |p|^2); |c-p|^2 = |c|^2 + |p|^2 - 2*dot; denom = 2*sqrt(sp2*sd2)+eps

#define C_CONST 100000
#define D_CONST 256
#define P_CONST 65536
#define K_CONST 4
#define BETA 0.1f
#define MARGIN 0.1f
#define EPS 1e-6f
#define PI_F 3.14159265358979f

#define WARPS_PER_BLOCK 8
#define THREADS_PER_BLOCK (WARPS_PER_BLOCK * 32)
#define NUM_BLOCKS (P_CONST / WARPS_PER_BLOCK)   // 8192

__device__ __align__(16) float g_partials[NUM_BLOCKS];
__device__ unsigned int g_count;   // zero-init; last block resets each call

__device__ __forceinline__ float sqrt_approx(float x) {
    float r; asm("sqrt.approx.f32 %0, %1;" : "=f"(r) : "f"(x)); return r;
}
__device__ __forceinline__ float rcp_approx(float x) {
    float r; asm("rcp.approx.f32 %0, %1;" : "=f"(r) : "f"(x)); return r;
}

// acos via A&S 4.4.45: acos(t) = sqrt(1-t)*poly7(t) for t in [0,1], |err| <= 2e-8.
// For x<0: acos(x) = pi - acos(-x). Input already clipped to [-1+eps, 1-eps].
__device__ __forceinline__ float acos_poly(float x) {
    float t = fabsf(x);
    float p = -0.0012624911f;
    p = fmaf(p, t,  0.0066700901f);
    p = fmaf(p, t, -0.0170881256f);
    p = fmaf(p, t,  0.0308918810f);
    p = fmaf(p, t, -0.0501743046f);
    p = fmaf(p, t,  0.0889789874f);
    p = fmaf(p, t, -0.2145988016f);
    p = fmaf(p, t,  1.5707963050f);
    float r = sqrt_approx(1.0f - t) * p;
    return (x >= 0.0f) ? r : (PI_F - r);
}

__global__ __launch_bounds__(THREADS_PER_BLOCK, 8)   // force <=32 regs -> 100% occ
void cone_loss_kernel(const float* __restrict__ protos,
                      const int*   __restrict__ pairs,
                      const int*   __restrict__ neg_c,
                      float*       __restrict__ out) {
    const int wid  = threadIdx.x >> 5;
    const int lane = threadIdx.x & 31;
    const int pair = blockIdx.x * WARPS_PER_BLOCK + wid;   // one warp per pair

    __shared__ float s_warp[WARPS_PER_BLOCK];

    // ---- indices ----
    const int2 pc   = __ldg(reinterpret_cast<const int2*>(pairs) + pair);
    const int4 nidx = __ldg(reinterpret_cast<const int4*>(neg_c) + pair);

    // ---- p row (256 floats): 2x float4 per lane ----
    const float4* pbase = reinterpret_cast<const float4*>(protos);
    const float4* prow  = pbase + (size_t)pc.x * (D_CONST / 4);
    const float4 pa = __ldg(&prow[lane]);
    const float4 pb = __ldg(&prow[lane + 32]);

    float sp2p = pa.x*pa.x + pa.y*pa.y + pa.z*pa.z + pa.w*pa.w
               + pb.x*pb.x + pb.y*pb.y + pb.z*pb.z + pb.w*pb.w;
    #pragma unroll
    for (int o = 16; o > 0; o >>= 1) sp2p += __shfl_xor_sync(0xFFFFFFFFu, sp2p, o);
    const float sp2    = sp2p;
    const float norm_p = sqrt_approx(sp2);

    // aperture: asin(sa), sa ~ 0.006 -> cubic Taylor (|err| < 1e-11)
    float sa = BETA / (norm_p + EPS);
    sa = fminf(fmaxf(sa, 0.0f), 1.0f - EPS);
    const float aperture = sa * (1.0f + sa * sa * (1.0f / 6.0f));

    // ---- 5 c-rows, serial ----
    float e_pos = 0.0f, neg_sum = 0.0f;
    #pragma unroll
    for (int r = 0; r < 5; r++) {
        int cidx = (r == 0) ? pc.y : ((r == 1) ? nidx.x : (r == 2) ? nidx.y
                                     : (r == 3) ? nidx.z : nidx.w);
        const float4* crow = pbase + (size_t)cidx * (D_CONST / 4);
        float4 ca = __ldg(&crow[lane]);
        float4 cb = __ldg(&crow[lane + 32]);

        float cc_p  = ca.x*ca.x + ca.y*ca.y + ca.z*ca.z + ca.w*ca.w
                    + cb.x*cb.x + cb.y*cb.y + cb.z*cb.z + cb.w*cb.w;
        float dot_p = ca.x*pa.x + ca.y*pa.y + ca.z*pa.z + ca.w*pa.w
                    + cb.x*pb.x + cb.y*pb.y + cb.z*pb.z + cb.w*pb.w;

        #pragma unroll
        for (int o = 16; o > 0; o >>= 1) {   // two interleaved butterflies
            cc_p  += __shfl_xor_sync(0xFFFFFFFFu, cc_p,  o);
            dot_p += __shfl_xor_sync(0xFFFFFFFFu, dot_p, o);
        }

        float sd2 = fmaxf(cc_p + sp2 - 2.0f * dot_p, 0.0f);
        float num = 2.0f * (dot_p - sp2);
        float denom  = 2.0f * sqrt_approx(sp2 * sd2) + EPS;  // sqrt.approx(0)=0 -> c==p edge OK
        float cosang = num * rcp_approx(denom);
        cosang = fminf(fmaxf(cosang, -1.0f + EPS), 1.0f - EPS);
        float e = fmaxf(acos_poly(cosang) - aperture, 0.0f);

        if (r == 0) e_pos = e;
        else        neg_sum += fmaxf(MARGIN - e, 0.0f);
    }

    if (lane == 0) {
        s_warp[wid] = 0.5f * (e_pos   * (1.0f / (float)P_CONST)
                            + neg_sum * (1.0f / ((float)P_CONST * (float)K_CONST)));
    }
    __syncthreads();

    // ---- per-block partial -> L2 via st.cg, release-acquire counter (no threadfence) ----
    __shared__ bool is_last;
    if (threadIdx.x == 0) {
        float bsum = 0.0f;
        #pragma unroll
        for (int w = 0; w < WARPS_PER_BLOCK; w++) bsum += s_warp[w];
        asm volatile("st.global.cg.f32 [%0], %1;"
                     :: "l"(&g_partials[blockIdx.x]), "f"(bsum) : "memory");
        unsigned int old;
        asm volatile("atom.acq_rel.gpu.global.add.u32 %0, [%1], %2;"
                     : "=r"(old) : "l"(&g_count), "r"(1u) : "memory");
        is_last = (old == (unsigned int)(NUM_BLOCKS - 1));
    }
    __syncthreads();

    // ---- last block: reduce 8192 partials from L2 ----
    if (is_last) {
        const float4* src = reinterpret_cast<const float4*>(g_partials);
        float r = 0.0f;
        #pragma unroll
        for (int j = 0; j < 8; j++) {   // 2048 float4 = 256 thr * 8
            float4 v = __ldcg(&src[threadIdx.x + j * THREADS_PER_BLOCK]);
            r += (v.x + v.y) + (v.z + v.w);
        }
        #pragma unroll
        for (int o = 16; o > 0; o >>= 1) r += __shfl_xor_sync(0xFFFFFFFFu, r, o);
        if (lane == 0) s_warp[wid] = r;
        __syncthreads();
        if (threadIdx.x == 0) {
            float tot = 0.0f;
            #pragma unroll
            for (int w = 0; w < WARPS_PER_BLOCK; w++) tot += s_warp[w];
            out[0] = tot;
            atomicExch(&g_count, 0u);   // reset for next graph replay
        }
    }
}

extern "C" void kernel_launch(void* const* d_in, const int* in_sizes, int n_in,
                              void* d_out, int out_size) {
    const float* protos = (const float*)d_in[0];
    const int*   pairs  = (const int*)d_in[1];
    const int*   negc   = (const int*)d_in[2];
    float* out = (float*)d_out;

    cone_loss_kernel<<<NUM_BLOCKS, THREADS_PER_BLOCK>>>(protos, pairs, negc, out);
}

// round 8
// speedup vs baseline: 1.2144x; 1.0054x over previous
#include <cuda_runtime.h>
#include <cstdint>

// EntailmentConeLoss: loss = 0.5*( mean_i E(p_i,cpos_i) + mean_{i,k} relu(MARGIN - E(p_i,cneg_{ik})) )
// E(p,c) = relu(acos(clip(num/denom)) - asin(clip(BETA/(|p|+eps),0,1-eps)))
// dot form: num = 2*(dot - |p|^2); |c-p|^2 = |c|^2 + |p|^2 - 2*dot; denom = 2*sqrt(sp2*sd2)+eps

#define C_CONST 100000
#define D_CONST 256
#define P_CONST 65536
#define K_CONST 4
#define BETA 0.1f
#define MARGIN 0.1f
#define EPS 1e-6f
#define PI_F 3.14159265358979f

#define WARPS_PER_BLOCK 8
#define THREADS_PER_BLOCK (WARPS_PER_BLOCK * 32)
#define NUM_BLOCKS (P_CONST / WARPS_PER_BLOCK)   // 8192

__device__ __align__(16) float g_partials[NUM_BLOCKS];
__device__ unsigned int g_count;   // zero-init; last block resets each call

__device__ __forceinline__ float sqrt_approx(float x) {
    float r; asm("sqrt.approx.f32 %0, %1;" : "=f"(r) : "f"(x)); return r;
}
__device__ __forceinline__ float rcp_approx(float x) {
    float r; asm("rcp.approx.f32 %0, %1;" : "=f"(r) : "f"(x)); return r;
}

// acos via A&S 4.4.45: acos(t) = sqrt(1-t)*poly7(t) for t in [0,1], |err| <= 2e-8.
// For x<0: acos(x) = pi - acos(-x). Input already clipped to [-1+eps, 1-eps].
__device__ __forceinline__ float acos_poly(float x) {
    float t = fabsf(x);
    float p = -0.0012624911f;
    p = fmaf(p, t,  0.0066700901f);
    p = fmaf(p, t, -0.0170881256f);
    p = fmaf(p, t,  0.0308918810f);
    p = fmaf(p, t, -0.0501743046f);
    p = fmaf(p, t,  0.0889789874f);
    p = fmaf(p, t, -0.2145988016f);
    p = fmaf(p, t,  1.5707963050f);
    float r = sqrt_approx(1.0f - t) * p;
    return (x >= 0.0f) ? r : (PI_F - r);
}

__global__ __launch_bounds__(THREADS_PER_BLOCK, 8)   // force <=32 regs -> 100% occ
void cone_loss_kernel(const float* __restrict__ protos,
                      const int*   __restrict__ pairs,
                      const int*   __restrict__ neg_c,
                      float*       __restrict__ out) {
    const int wid  = threadIdx.x >> 5;
    const int lane = threadIdx.x & 31;
    const int pair = blockIdx.x * WARPS_PER_BLOCK + wid;   // one warp per pair

    __shared__ float s_warp[WARPS_PER_BLOCK];

    // ---- indices ----
    const int2 pc   = __ldg(reinterpret_cast<const int2*>(pairs) + pair);
    const int4 nidx = __ldg(reinterpret_cast<const int4*>(neg_c) + pair);

    // ---- p row (256 floats): 2x float4 per lane ----
    const float4* pbase = reinterpret_cast<const float4*>(protos);
    const float4* prow  = pbase + (size_t)pc.x * (D_CONST / 4);
    const float4 pa = __ldg(&prow[lane]);
    const float4 pb = __ldg(&prow[lane + 32]);

    float sp2p = pa.x*pa.x + pa.y*pa.y + pa.z*pa.z + pa.w*pa.w
               + pb.x*pb.x + pb.y*pb.y + pb.z*pb.z + pb.w*pb.w;
    #pragma unroll
    for (int o = 16; o > 0; o >>= 1) sp2p += __shfl_xor_sync(0xFFFFFFFFu, sp2p, o);
    const float sp2    = sp2p;
    const float norm_p = sqrt_approx(sp2);

    // aperture: asin(sa), sa ~ 0.006 -> cubic Taylor (|err| < 1e-11)
    float sa = BETA / (norm_p + EPS);
    sa = fminf(fmaxf(sa, 0.0f), 1.0f - EPS);
    const float aperture = sa * (1.0f + sa * sa * (1.0f / 6.0f));

    // ---- 5 c-rows, serial ----
    float e_pos = 0.0f, neg_sum = 0.0f;
    #pragma unroll
    for (int r = 0; r < 5; r++) {
        int cidx = (r == 0) ? pc.y : ((r == 1) ? nidx.x : (r == 2) ? nidx.y
                                     : (r == 3) ? nidx.z : nidx.w);
        const float4* crow = pbase + (size_t)cidx * (D_CONST / 4);
        float4 ca = __ldg(&crow[lane]);
        float4 cb = __ldg(&crow[lane + 32]);

        float cc_p  = ca.x*ca.x + ca.y*ca.y + ca.z*ca.z + ca.w*ca.w
                    + cb.x*cb.x + cb.y*cb.y + cb.z*cb.z + cb.w*cb.w;
        float dot_p = ca.x*pa.x + ca.y*pa.y + ca.z*pa.z + ca.w*pa.w
                    + cb.x*pb.x + cb.y*pb.y + cb.z*pb.z + cb.w*pb.w;

        #pragma unroll
        for (int o = 16; o > 0; o >>= 1) {   // two interleaved butterflies
            cc_p  += __shfl_xor_sync(0xFFFFFFFFu, cc_p,  o);
            dot_p += __shfl_xor_sync(0xFFFFFFFFu, dot_p, o);
        }

        float sd2 = fmaxf(cc_p + sp2 - 2.0f * dot_p, 0.0f);
        float num = 2.0f * (dot_p - sp2);
        float denom  = 2.0f * sqrt_approx(sp2 * sd2) + EPS;  // sqrt.approx(0)=0 -> c==p edge OK
        float cosang = num * rcp_approx(denom);
        cosang = fminf(fmaxf(cosang, -1.0f + EPS), 1.0f - EPS);
        float e = fmaxf(acos_poly(cosang) - aperture, 0.0f);

        if (r == 0) e_pos = e;
        else        neg_sum += fmaxf(MARGIN - e, 0.0f);
    }

    if (lane == 0) {
        s_warp[wid] = 0.5f * (e_pos   * (1.0f / (float)P_CONST)
                            + neg_sum * (1.0f / ((float)P_CONST * (float)K_CONST)));
    }
    __syncthreads();

    // ---- per-block partial -> L2 via st.cg, release-acquire counter (no threadfence) ----
    __shared__ bool is_last;
    if (threadIdx.x == 0) {
        float bsum = 0.0f;
        #pragma unroll
        for (int w = 0; w < WARPS_PER_BLOCK; w++) bsum += s_warp[w];
        asm volatile("st.global.cg.f32 [%0], %1;"
                     :: "l"(&g_partials[blockIdx.x]), "f"(bsum) : "memory");
        unsigned int old;
        asm volatile("atom.acq_rel.gpu.global.add.u32 %0, [%1], %2;"
                     : "=r"(old) : "l"(&g_count), "r"(1u) : "memory");
        is_last = (old == (unsigned int)(NUM_BLOCKS - 1));
    }
    __syncthreads();

    // ---- last block: reduce 8192 partials from L2 ----
    if (is_last) {
        const float4* src = reinterpret_cast<const float4*>(g_partials);
        float r = 0.0f;
        #pragma unroll
        for (int j = 0; j < 8; j++) {   // 2048 float4 = 256 thr * 8
            float4 v = __ldcg(&src[threadIdx.x + j * THREADS_PER_BLOCK]);
            r += (v.x + v.y) + (v.z + v.w);
        }
        #pragma unroll
        for (int o = 16; o > 0; o >>= 1) r += __shfl_xor_sync(0xFFFFFFFFu, r, o);
        if (lane == 0) s_warp[wid] = r;
        __syncthreads();
        if (threadIdx.x == 0) {
            float tot = 0.0f;
            #pragma unroll
            for (int w = 0; w < WARPS_PER_BLOCK; w++) tot += s_warp[w];
            out[0] = tot;
            atomicExch(&g_count, 0u);   // reset for next graph replay
        }
    }
}

extern "C" void kernel_launch(void* const* d_in, const int* in_sizes, int n_in,
                              void* d_out, int out_size) {
    const float* protos = (const float*)d_in[0];
    const int*   pairs  = (const int*)d_in[1];
    const int*   negc   = (const int*)d_in[2];
    float* out = (float*)d_out;

    cone_loss_kernel<<<NUM_BLOCKS, THREADS_PER_BLOCK>>>(protos, pairs, negc, out);
}